// round 14
// baseline (speedup 1.0000x reference)
#include <cuda_runtime.h>
#include <cuda_fp16.h>
#include <math.h>

#define B_ 4
#define T_ 256
#define N_ 48
#define F_ 4
#define H_ 64
#define K_ 4
#define E_ 192
#define LH_ 512
#define C_ 8
#define G_ (B_*T_)     // 1024
#define KH_ (K_*H_)    // 256
#define KHP_ (KH_+1)
#define NH_ (N_*H_)    // 3072
#define G4_ (4*LH_)    // 2048
#define NEG_SLOPE 0.2f

#define CLU 16                 // CTAs per cluster (one cluster per batch)
#define LROWS 128              // W rows per CTA (32 j x 4 gates)
#define WQ 136                 // halfs per quarter-section (128 + 8 pad)
#define WSTR (4*WQ)            // 544 halfs per W row (1088 B)
#define HSTR (4*WQ)            // 544 floats per h buffer
#define SW_BYTES (LROWS*WSTR*2)   // 139264

// ---------------- scratch ----------------------------------------------------
__device__ float g_h1[G_*N_*KH_];
__device__ float g_seq[G_*NH_];
__device__ float g_xw[G_*G4_];
__device__ float g_hbuf[2][B_][LH_];
__device__ int   g_coff[N_+1];
__device__ int   g_ceid[E_];

// ---------------- deterministic CSR build ------------------------------------
__global__ void build_csr_kernel(const int* __restrict__ ei)
{
    __shared__ int sdst[E_];
    __shared__ int sdeg[N_];
    __shared__ int soff[N_+1];
    int tid = threadIdx.x;
    for (int e = tid; e < E_; e += blockDim.x) sdst[e] = ei[E_ + e];
    __syncthreads();
    for (int n = tid; n < N_; n += blockDim.x) {
        int d = 0;
        for (int e = 0; e < E_; e++) d += (sdst[e] == n);
        sdeg[n] = d;
    }
    __syncthreads();
    if (tid == 0) {
        int acc = 0;
        for (int n = 0; n < N_; n++) { soff[n] = acc; acc += sdeg[n]; }
        soff[N_] = acc;
    }
    __syncthreads();
    for (int n = tid; n < N_; n += blockDim.x) {
        int p = soff[n];
        for (int e = 0; e < E_; e++) if (sdst[e] == n) g_ceid[p++] = e;
    }
    for (int n = tid; n <= N_; n += blockDim.x) g_coff[n] = soff[n];
}

// ---------------- GAT layer 1 ------------------------------------------------
__global__ __launch_bounds__(256) void gat1_kernel(
    const float* __restrict__ x, const int* __restrict__ ei,
    const float* __restrict__ Wl, const float* __restrict__ Wr,
    const float* __restrict__ att, const float* __restrict__ bias)
{
    extern __shared__ float sm[];
    float* xl   = sm;
    float* xr   = xl + N_*KHP_;
    float* wl   = xr + N_*KHP_;
    float* wr   = wl + F_*KH_;
    float* satt = wr + F_*KH_;
    float* sb   = satt + KH_;
    float* sx   = sb + KH_;
    float* se   = sx + N_*F_;
    int* ssrc = (int*)(se + E_*K_);
    int* sdst = ssrc + E_;
    int* soff = sdst + E_;
    int* seid = soff + (N_+1);

    int g = blockIdx.x;
    int tid = threadIdx.x;

    for (int i = tid; i < F_*KH_; i += 256) { wl[i] = Wl[i]; wr[i] = Wr[i]; }
    satt[tid] = att[tid];
    sb[tid] = bias[tid];
    for (int i = tid; i < N_*F_; i += 256) sx[i] = x[(size_t)g*N_*F_ + i];
    for (int i = tid; i < E_; i += 256) { ssrc[i] = ei[i]; sdst[i] = ei[E_+i]; seid[i] = g_ceid[i]; }
    for (int i = tid; i <= N_; i += 256) soff[i] = g_coff[i];
    __syncthreads();

    const int o = tid;
    for (int n = 0; n < N_; n++) {
        float al = 0.f, ar = 0.f;
        #pragma unroll
        for (int f = 0; f < F_; f++) {
            float xv = sx[n*F_ + f];
            al += xv * wl[f*KH_ + o];
            ar += xv * wr[f*KH_ + o];
        }
        xl[n*KHP_ + o] = al;
        xr[n*KHP_ + o] = ar;
    }
    __syncthreads();

    for (int idx = tid; idx < E_*K_; idx += 256) {
        int e = idx >> 2, k = idx & 3;
        const float* pl = xl + ssrc[e]*KHP_ + k*H_;
        const float* pr = xr + sdst[e]*KHP_ + k*H_;
        const float* pa = satt + k*H_;
        float acc = 0.f;
        #pragma unroll 8
        for (int h = 0; h < H_; h++) {
            float v = pl[h] + pr[h];
            v = v > 0.f ? v : NEG_SLOPE * v;
            acc += v * pa[h];
        }
        se[idx] = acc;
    }
    __syncthreads();

    for (int idx = tid; idx < N_*K_; idx += 256) {
        int n = idx >> 2, k = idx & 3;
        int a0 = soff[n], a1 = soff[n+1];
        float mx = -1e30f;
        for (int a = a0; a < a1; a++) mx = fmaxf(mx, se[seid[a]*K_ + k]);
        float s = 0.f;
        for (int a = a0; a < a1; a++) s += expf(se[seid[a]*K_ + k] - mx);
        float inv = 1.f / (s + 1e-16f);
        for (int a = a0; a < a1; a++) {
            int j = seid[a]*K_ + k;
            se[j] = expf(se[j] - mx) * inv;
        }
    }
    __syncthreads();

    int k = o >> 6;
    float* outp = g_h1 + (size_t)g*N_*KH_;
    for (int n = 0; n < N_; n++) {
        int a0 = soff[n], a1 = soff[n+1];
        float acc = 0.f;
        for (int a = a0; a < a1; a++) {
            int e = seid[a];
            acc += se[e*K_ + k] * xl[ssrc[e]*KHP_ + o];
        }
        outp[n*KH_ + o] = fmaxf(acc + sb[o], 0.f);
    }
}

// ---------------- GAT layer 2 (fused fp32, proven) ----------------------------
__global__ __launch_bounds__(256) void gat2_kernel(
    const int* __restrict__ ei,
    const float* __restrict__ Wl, const float* __restrict__ Wr,
    const float* __restrict__ att, const float* __restrict__ bias)
{
    extern __shared__ float sm[];
    float* sh_in = sm;
    float* xl    = sh_in + N_*KH_;
    float* xr    = xl + N_*KHP_;
    float* satt  = xr + N_*KHP_;
    float* sb    = satt + KH_;
    float* se    = sb + H_;
    int* ssrc = (int*)(se + E_*K_);
    int* sdst = ssrc + E_;
    int* soff = sdst + E_;
    int* seid = soff + (N_+1);

    int g = blockIdx.x;
    int tid = threadIdx.x;

    const float* h1p = g_h1 + (size_t)g*N_*KH_;
    for (int i = tid; i < N_*KH_; i += 256) sh_in[i] = h1p[i];
    satt[tid] = att[tid];
    if (tid < H_) sb[tid] = bias[tid];
    for (int i = tid; i < E_; i += 256) { ssrc[i] = ei[i]; sdst[i] = ei[E_+i]; seid[i] = g_ceid[i]; }
    for (int i = tid; i <= N_; i += 256) soff[i] = g_coff[i];
    __syncthreads();

    const int o = tid;
    {
        float acc[N_];
        #pragma unroll
        for (int n = 0; n < N_; n++) acc[n] = 0.f;
        #pragma unroll 2
        for (int i = 0; i < KH_; i++) {
            float w = Wl[i*KH_ + o];
            #pragma unroll
            for (int n = 0; n < N_; n++) acc[n] += sh_in[n*KH_ + i] * w;
        }
        #pragma unroll
        for (int n = 0; n < N_; n++) xl[n*KHP_ + o] = acc[n];
    }
    {
        float acc[N_];
        #pragma unroll
        for (int n = 0; n < N_; n++) acc[n] = 0.f;
        #pragma unroll 2
        for (int i = 0; i < KH_; i++) {
            float w = Wr[i*KH_ + o];
            #pragma unroll
            for (int n = 0; n < N_; n++) acc[n] += sh_in[n*KH_ + i] * w;
        }
        #pragma unroll
        for (int n = 0; n < N_; n++) xr[n*KHP_ + o] = acc[n];
    }
    __syncthreads();

    for (int idx = tid; idx < E_*K_; idx += 256) {
        int e = idx >> 2, k = idx & 3;
        const float* pl = xl + ssrc[e]*KHP_ + k*H_;
        const float* pr = xr + sdst[e]*KHP_ + k*H_;
        const float* pa = satt + k*H_;
        float acc = 0.f;
        #pragma unroll 8
        for (int h = 0; h < H_; h++) {
            float v = pl[h] + pr[h];
            v = v > 0.f ? v : NEG_SLOPE * v;
            acc += v * pa[h];
        }
        se[idx] = acc;
    }
    __syncthreads();

    for (int idx = tid; idx < N_*K_; idx += 256) {
        int n = idx >> 2, k = idx & 3;
        int a0 = soff[n], a1 = soff[n+1];
        float mx = -1e30f;
        for (int a = a0; a < a1; a++) mx = fmaxf(mx, se[seid[a]*K_ + k]);
        float s = 0.f;
        for (int a = a0; a < a1; a++) s += expf(se[seid[a]*K_ + k] - mx);
        float inv = 1.f / (s + 1e-16f);
        for (int a = a0; a < a1; a++) {
            int j = seid[a]*K_ + k;
            se[j] = expf(se[j] - mx) * inv;
        }
    }
    __syncthreads();

    for (int idx = tid; idx < N_*H_; idx += 256) {
        int n = idx >> 6, h = idx & 63;
        int a0 = soff[n], a1 = soff[n+1];
        float acc = 0.f;
        for (int a = a0; a < a1; a++) {
            int e = seid[a]; int s = ssrc[e];
            #pragma unroll
            for (int k2 = 0; k2 < K_; k2++)
                acc += se[e*K_ + k2] * xl[s*KHP_ + k2*H_ + h];
        }
        float v = acc * 0.25f + sb[h];
        g_seq[(size_t)g*NH_ + n*H_ + h] = fmaxf(v, 0.f);
    }
}

// ---------------- xw GEMM (proven 64x64x32 fp32) ------------------------------
#define BM 64
#define BN 64
#define BK 32
#define BMP (BM+4)
#define BNP (BN+4)
__global__ __launch_bounds__(256) void xw_gemm_kernel(
    const float* __restrict__ W_ih,
    const float* __restrict__ b_ih, const float* __restrict__ b_hh)
{
    __shared__ float As[BK][BMP];
    __shared__ float Bs[BK][BNP];
    int bn = blockIdx.x, bm = blockIdx.y;
    int tid = threadIdx.x;
    int tx = tid & 15, ty = tid >> 4;
    float acc[4][4] = {};
    const float* A0 = g_seq + (size_t)(bm*BM)*NH_;
    const float* B0 = W_ih + (size_t)(bn*BN)*NH_;
    int lr = tid >> 3;
    int lc = (tid & 7) * 4;

    for (int k0 = 0; k0 < NH_; k0 += BK) {
        #pragma unroll
        for (int half = 0; half < 2; half++) {
            int r = lr + half*32;
            float4 a4 = *(const float4*)&A0[(size_t)r*NH_ + k0 + lc];
            As[lc+0][r] = a4.x; As[lc+1][r] = a4.y;
            As[lc+2][r] = a4.z; As[lc+3][r] = a4.w;
            float4 b4 = *(const float4*)&B0[(size_t)r*NH_ + k0 + lc];
            Bs[lc+0][r] = b4.x; Bs[lc+1][r] = b4.y;
            Bs[lc+2][r] = b4.z; Bs[lc+3][r] = b4.w;
        }
        __syncthreads();
        #pragma unroll
        for (int k = 0; k < BK; k++) {
            float4 av = *(const float4*)&As[k][ty*4];
            float4 bv = *(const float4*)&Bs[k][tx*4];
            float a[4] = {av.x, av.y, av.z, av.w};
            float b[4] = {bv.x, bv.y, bv.z, bv.w};
            #pragma unroll
            for (int i = 0; i < 4; i++)
                #pragma unroll
                for (int j = 0; j < 4; j++)
                    acc[i][j] += a[i] * b[j];
        }
        __syncthreads();
    }
    #pragma unroll
    for (int i = 0; i < 4; i++) {
        int r = bm*BM + ty*4 + i;
        int c = bn*BN + tx*4;
        float4 o;
        o.x = acc[i][0] + b_ih[c+0] + b_hh[c+0];
        o.y = acc[i][1] + b_ih[c+1] + b_hh[c+1];
        o.z = acc[i][2] + b_ih[c+2] + b_hh[c+2];
        o.w = acc[i][3] + b_ih[c+3] + b_hh[c+3];
        *(float4*)&g_xw[(size_t)r*G4_ + c] = o;
    }
}

// ---------------- cluster LSTM v3: 512 thr, 4-way row split -------------------
__device__ __forceinline__ float sigm(float x) { return 1.f / (1.f + expf(-x)); }

__device__ __forceinline__ unsigned smem_u32(const void* p)
{
    unsigned a;
    asm("{ .reg .u64 t; cvta.to.shared.u64 t, %1; cvt.u32.u64 %0, t; }"
        : "=r"(a) : "l"(p));
    return a;
}
__device__ __forceinline__ unsigned my_cluster_rank()
{
    unsigned r;
    asm("mov.u32 %0, %%cluster_ctarank;" : "=r"(r));
    return r;
}
__device__ __forceinline__ void dsmem_store_f32(unsigned laddr, unsigned rank, float v)
{
    asm volatile(
        "{ .reg .b32 ra; mapa.shared::cluster.u32 ra, %0, %1; "
        "st.shared::cluster.f32 [ra], %2; }"
        :: "r"(laddr), "r"(rank), "f"(v) : "memory");
}

__global__ __launch_bounds__(512, 1) void lstm_cluster_kernel(const float* __restrict__ W_hh)
{
    extern __shared__ char smc[];
    __half* sw  = (__half*)smc;                  // [128][4][WQ] halfs
    float* hbuf = (float*)(smc + SW_BYTES);      // [2][HSTR] floats
    float* sval = hbuf + 2*HSTR;                 // 128

    const int tid  = threadIdx.x;
    const int b    = blockIdx.x / CLU;
    const unsigned rank = my_cluster_rank();     // 0..15
    const int j0   = rank * 32;

    // load W slice as fp16 into [row][quarter][WQ] layout
    for (int idx = tid; idx < LROWS*256; idx += 512) {
        int r  = idx >> 8;            // row 0..127
        int i2 = idx & 255;           // half2 index within row (512 halfs)
        int gate = r >> 5, jr = r & 31;
        float2 wv = *(const float2*)&W_hh[(size_t)(gate*LH_ + j0 + jr)*LH_ + i2*2];
        int q = i2 >> 6;              // quarter 0..3
        int k = (i2 & 63)*2;          // half offset within quarter
        *(__half2*)&sw[r*WSTR + q*WQ + k] = __floats2half2_rn(wv.x, wv.y);
    }
    for (int i = tid; i < 2*HSTR; i += 512) hbuf[i] = 0.f;
    __syncthreads();

    const int row = tid >> 2, q = tid & 3;       // 4 threads per row
    const int gate = row >> 5, jr = row & 31;
    const uint4* wv = (const uint4*)(sw + row*WSTR + q*WQ);   // 16 x 8 halfs
    const float* xp = g_xw + (size_t)(b*T_)*G4_ + gate*LH_ + j0 + jr;
    const unsigned hbuf_addr = smem_u32(hbuf);

    float xval = (q == 0) ? __ldcg(xp) : 0.f;
    float c = 0.f;                               // cell state (tid < 32)

    for (int t = 0; t < T_; t++) {
        const float4* hv = (const float4*)(hbuf + (t & 1)*HSTR + q*WQ);
        float a0 = 0.f, a1 = 0.f, a2 = 0.f, a3 = 0.f;
        #pragma unroll
        for (int i = 0; i < 16; i++) {
            uint4 w = wv[i];
            float4 p = hv[2*i], r4 = hv[2*i+1];
            float2 w0 = __half22float2(*(__half2*)&w.x);
            float2 w1 = __half22float2(*(__half2*)&w.y);
            float2 w2 = __half22float2(*(__half2*)&w.z);
            float2 w3 = __half22float2(*(__half2*)&w.w);
            a0 = fmaf(w0.x, p.x, a0);  a1 = fmaf(w0.y, p.y, a1);
            a2 = fmaf(w1.x, p.z, a2);  a3 = fmaf(w1.y, p.w, a3);
            a0 = fmaf(w2.x, r4.x, a0); a1 = fmaf(w2.y, r4.y, a1);
            a2 = fmaf(w3.x, r4.z, a2); a3 = fmaf(w3.y, r4.w, a3);
        }
        float s = (a0 + a1) + (a2 + a3);
        s += __shfl_xor_sync(0xffffffffu, s, 1);
        s += __shfl_xor_sync(0xffffffffu, s, 2);
        if (q == 0) sval[row] = s + xval;
        __syncthreads();

        if (tid < 32) {
            float gi = sval[tid];
            float gf = sval[32 + tid];
            float gg = sval[64 + tid];
            float go = sval[96 + tid];
            c = sigm(gf)*c + sigm(gi)*tanhf(gg);
            float h = sigm(go)*tanhf(c);
            if (t == T_-1) {
                g_hbuf[0][b][j0 + tid] = h;
            } else {
                int jg = j0 + tid;
                int qd = jg >> 7, kd = jg & 127;
                unsigned dst = hbuf_addr
                             + (unsigned)(((t + 1) & 1)*HSTR + qd*WQ + kd)*4u;
                #pragma unroll
                for (int d = 0; d < CLU; d++)
                    dsmem_store_f32(dst, (unsigned)d, h);
            }
        }
        if (t < T_-1) {
            if (q == 0) xval = __ldcg(xp + (size_t)(t + 1)*G4_);
            asm volatile("barrier.cluster.arrive.aligned;" ::: "memory");
            asm volatile("barrier.cluster.wait.aligned;" ::: "memory");
        }
    }
    asm volatile("barrier.cluster.arrive.aligned;" ::: "memory");
    asm volatile("barrier.cluster.wait.aligned;" ::: "memory");
}

// ---------------- final fc -----------------------------------------------------
__global__ void fc_kernel(const float* __restrict__ fc_w,
                          const float* __restrict__ fc_b,
                          float* __restrict__ out)
{
    int tid = threadIdx.x;
    if (tid < B_*C_) {
        int b = tid >> 3, c = tid & 7;
        const float* h = g_hbuf[0][b];
        const float* w = fc_w + c*LH_;
        float acc = 0.f;
        for (int j = 0; j < LH_; j++) acc += h[j] * w[j];
        out[b*C_ + c] = acc + fc_b[c];
    }
}

// ---------------- launch -------------------------------------------------------
extern "C" void kernel_launch(void* const* d_in, const int* in_sizes, int n_in,
                              void* d_out, int out_size)
{
    (void)in_sizes; (void)n_in; (void)out_size;
    const float* x    = (const float*)d_in[0];
    const int*   ei   = (const int*)d_in[1];
    const float* Wl1  = (const float*)d_in[2];
    const float* Wr1  = (const float*)d_in[3];
    const float* att1 = (const float*)d_in[4];
    const float* b1   = (const float*)d_in[5];
    const float* Wl2  = (const float*)d_in[6];
    const float* Wr2  = (const float*)d_in[7];
    const float* att2 = (const float*)d_in[8];
    const float* b2   = (const float*)d_in[9];
    const float* W_ih = (const float*)d_in[10];
    const float* W_hh = (const float*)d_in[11];
    const float* b_ih = (const float*)d_in[12];
    const float* b_hh = (const float*)d_in[13];
    const float* fc_w = (const float*)d_in[14];
    const float* fc_b = (const float*)d_in[15];
    float* out = (float*)d_out;

    const size_t sm1 = (size_t)(2*N_*KHP_ + 2*F_*KH_ + 2*KH_ + N_*F_ + E_*K_) * 4
                     + (size_t)(2*E_ + (N_+1) + E_) * 4;
    const size_t sm2 = (size_t)(N_*KH_ + 2*N_*KHP_ + KH_ + H_ + E_*K_) * 4
                     + (size_t)(2*E_ + (N_+1) + E_) * 4;
    const size_t sml = SW_BYTES + (size_t)(2*HSTR + LROWS) * 4;

    cudaFuncSetAttribute(gat1_kernel, cudaFuncAttributeMaxDynamicSharedMemorySize, (int)sm1);
    cudaFuncSetAttribute(gat2_kernel, cudaFuncAttributeMaxDynamicSharedMemorySize, (int)sm2);
    cudaFuncSetAttribute(lstm_cluster_kernel, cudaFuncAttributeMaxDynamicSharedMemorySize, (int)sml);
    cudaFuncSetAttribute(lstm_cluster_kernel, cudaFuncAttributeNonPortableClusterSizeAllowed, 1);

    build_csr_kernel<<<1, 64>>>(ei);
    gat1_kernel<<<G_, 256, sm1>>>(x, ei, Wl1, Wr1, att1, b1);
    gat2_kernel<<<G_, 256, sm2>>>(ei, Wl2, Wr2, att2, b2);
    dim3 gx(G4_/BN, G_/BM);
    xw_gemm_kernel<<<gx, 256>>>(W_ih, b_ih, b_hh);

    {
        cudaLaunchConfig_t cfg = {};
        cfg.gridDim  = dim3(B_*CLU, 1, 1);     // 64 CTAs = 4 clusters of 16
        cfg.blockDim = dim3(512, 1, 1);
        cfg.dynamicSmemBytes = sml;
        cfg.stream = 0;
        cudaLaunchAttribute attrs[1];
        attrs[0].id = cudaLaunchAttributeClusterDimension;
        attrs[0].val.clusterDim.x = CLU;
        attrs[0].val.clusterDim.y = 1;
        attrs[0].val.clusterDim.z = 1;
        cfg.attrs = attrs;
        cfg.numAttrs = 1;
        cudaLaunchKernelEx(&cfg, lstm_cluster_kernel, W_hh);
    }

    fc_kernel<<<1, 32>>>(fc_w, fc_b, out);
}

// round 15
// speedup vs baseline: 1.0393x; 1.0393x over previous
#include <cuda_runtime.h>
#include <cuda_fp16.h>
#include <math.h>

#define B_ 4
#define T_ 256
#define N_ 48
#define F_ 4
#define H_ 64
#define K_ 4
#define E_ 192
#define LH_ 512
#define C_ 8
#define G_ (B_*T_)     // 1024
#define KH_ (K_*H_)    // 256
#define KHP_ (KH_+1)
#define NH_ (N_*H_)    // 3072
#define G4_ (4*LH_)    // 2048
#define NEG_SLOPE 0.2f

#define CLU 16                 // CTAs per cluster (one cluster per batch)
#define LROWS 128              // W rows per CTA (32 j x 4 gates)
#define WSTR 528               // halfs per W row (2 sections of 264)
#define HSEC 264               // floats per h half-section
#define SW_BYTES (LROWS*WSTR*2)   // 135168

// ---------------- scratch ----------------------------------------------------
__device__ float g_h1[G_*N_*KH_];
__device__ float g_seq[G_*NH_];
__device__ float g_xw[G_*G4_];
__device__ float g_hbuf[2][B_][LH_];
__device__ int   g_coff[N_+1];
__device__ int   g_ceid[E_];

// ---------------- deterministic CSR build ------------------------------------
__global__ void build_csr_kernel(const int* __restrict__ ei)
{
    __shared__ int sdst[E_];
    __shared__ int sdeg[N_];
    __shared__ int soff[N_+1];
    int tid = threadIdx.x;
    for (int e = tid; e < E_; e += blockDim.x) sdst[e] = ei[E_ + e];
    __syncthreads();
    for (int n = tid; n < N_; n += blockDim.x) {
        int d = 0;
        for (int e = 0; e < E_; e++) d += (sdst[e] == n);
        sdeg[n] = d;
    }
    __syncthreads();
    if (tid == 0) {
        int acc = 0;
        for (int n = 0; n < N_; n++) { soff[n] = acc; acc += sdeg[n]; }
        soff[N_] = acc;
    }
    __syncthreads();
    for (int n = tid; n < N_; n += blockDim.x) {
        int p = soff[n];
        for (int e = 0; e < E_; e++) if (sdst[e] == n) g_ceid[p++] = e;
    }
    for (int n = tid; n <= N_; n += blockDim.x) g_coff[n] = soff[n];
}

// ---------------- GAT layer 1 ------------------------------------------------
__global__ __launch_bounds__(256) void gat1_kernel(
    const float* __restrict__ x, const int* __restrict__ ei,
    const float* __restrict__ Wl, const float* __restrict__ Wr,
    const float* __restrict__ att, const float* __restrict__ bias)
{
    extern __shared__ float sm[];
    float* xl   = sm;
    float* xr   = xl + N_*KHP_;
    float* wl   = xr + N_*KHP_;
    float* wr   = wl + F_*KH_;
    float* satt = wr + F_*KH_;
    float* sb   = satt + KH_;
    float* sx   = sb + KH_;
    float* se   = sx + N_*F_;
    int* ssrc = (int*)(se + E_*K_);
    int* sdst = ssrc + E_;
    int* soff = sdst + E_;
    int* seid = soff + (N_+1);

    int g = blockIdx.x;
    int tid = threadIdx.x;

    for (int i = tid; i < F_*KH_; i += 256) { wl[i] = Wl[i]; wr[i] = Wr[i]; }
    satt[tid] = att[tid];
    sb[tid] = bias[tid];
    for (int i = tid; i < N_*F_; i += 256) sx[i] = x[(size_t)g*N_*F_ + i];
    for (int i = tid; i < E_; i += 256) { ssrc[i] = ei[i]; sdst[i] = ei[E_+i]; seid[i] = g_ceid[i]; }
    for (int i = tid; i <= N_; i += 256) soff[i] = g_coff[i];
    __syncthreads();

    const int o = tid;
    for (int n = 0; n < N_; n++) {
        float al = 0.f, ar = 0.f;
        #pragma unroll
        for (int f = 0; f < F_; f++) {
            float xv = sx[n*F_ + f];
            al += xv * wl[f*KH_ + o];
            ar += xv * wr[f*KH_ + o];
        }
        xl[n*KHP_ + o] = al;
        xr[n*KHP_ + o] = ar;
    }
    __syncthreads();

    for (int idx = tid; idx < E_*K_; idx += 256) {
        int e = idx >> 2, k = idx & 3;
        const float* pl = xl + ssrc[e]*KHP_ + k*H_;
        const float* pr = xr + sdst[e]*KHP_ + k*H_;
        const float* pa = satt + k*H_;
        float acc = 0.f;
        #pragma unroll 8
        for (int h = 0; h < H_; h++) {
            float v = pl[h] + pr[h];
            v = v > 0.f ? v : NEG_SLOPE * v;
            acc += v * pa[h];
        }
        se[idx] = acc;
    }
    __syncthreads();

    for (int idx = tid; idx < N_*K_; idx += 256) {
        int n = idx >> 2, k = idx & 3;
        int a0 = soff[n], a1 = soff[n+1];
        float mx = -1e30f;
        for (int a = a0; a < a1; a++) mx = fmaxf(mx, se[seid[a]*K_ + k]);
        float s = 0.f;
        for (int a = a0; a < a1; a++) s += expf(se[seid[a]*K_ + k] - mx);
        float inv = 1.f / (s + 1e-16f);
        for (int a = a0; a < a1; a++) {
            int j = seid[a]*K_ + k;
            se[j] = expf(se[j] - mx) * inv;
        }
    }
    __syncthreads();

    int k = o >> 6;
    float* outp = g_h1 + (size_t)g*N_*KH_;
    for (int n = 0; n < N_; n++) {
        int a0 = soff[n], a1 = soff[n+1];
        float acc = 0.f;
        for (int a = a0; a < a1; a++) {
            int e = seid[a];
            acc += se[e*K_ + k] * xl[ssrc[e]*KHP_ + o];
        }
        outp[n*KH_ + o] = fmaxf(acc + sb[o], 0.f);
    }
}

// ---------------- GAT layer 2 (fused fp32, proven) ----------------------------
__global__ __launch_bounds__(256) void gat2_kernel(
    const int* __restrict__ ei,
    const float* __restrict__ Wl, const float* __restrict__ Wr,
    const float* __restrict__ att, const float* __restrict__ bias)
{
    extern __shared__ float sm[];
    float* sh_in = sm;
    float* xl    = sh_in + N_*KH_;
    float* xr    = xl + N_*KHP_;
    float* satt  = xr + N_*KHP_;
    float* sb    = satt + KH_;
    float* se    = sb + H_;
    int* ssrc = (int*)(se + E_*K_);
    int* sdst = ssrc + E_;
    int* soff = sdst + E_;
    int* seid = soff + (N_+1);

    int g = blockIdx.x;
    int tid = threadIdx.x;

    const float* h1p = g_h1 + (size_t)g*N_*KH_;
    for (int i = tid; i < N_*KH_; i += 256) sh_in[i] = h1p[i];
    satt[tid] = att[tid];
    if (tid < H_) sb[tid] = bias[tid];
    for (int i = tid; i < E_; i += 256) { ssrc[i] = ei[i]; sdst[i] = ei[E_+i]; seid[i] = g_ceid[i]; }
    for (int i = tid; i <= N_; i += 256) soff[i] = g_coff[i];
    __syncthreads();

    const int o = tid;
    {
        float acc[N_];
        #pragma unroll
        for (int n = 0; n < N_; n++) acc[n] = 0.f;
        #pragma unroll 2
        for (int i = 0; i < KH_; i++) {
            float w = Wl[i*KH_ + o];
            #pragma unroll
            for (int n = 0; n < N_; n++) acc[n] += sh_in[n*KH_ + i] * w;
        }
        #pragma unroll
        for (int n = 0; n < N_; n++) xl[n*KHP_ + o] = acc[n];
    }
    {
        float acc[N_];
        #pragma unroll
        for (int n = 0; n < N_; n++) acc[n] = 0.f;
        #pragma unroll 2
        for (int i = 0; i < KH_; i++) {
            float w = Wr[i*KH_ + o];
            #pragma unroll
            for (int n = 0; n < N_; n++) acc[n] += sh_in[n*KH_ + i] * w;
        }
        #pragma unroll
        for (int n = 0; n < N_; n++) xr[n*KHP_ + o] = acc[n];
    }
    __syncthreads();

    for (int idx = tid; idx < E_*K_; idx += 256) {
        int e = idx >> 2, k = idx & 3;
        const float* pl = xl + ssrc[e]*KHP_ + k*H_;
        const float* pr = xr + sdst[e]*KHP_ + k*H_;
        const float* pa = satt + k*H_;
        float acc = 0.f;
        #pragma unroll 8
        for (int h = 0; h < H_; h++) {
            float v = pl[h] + pr[h];
            v = v > 0.f ? v : NEG_SLOPE * v;
            acc += v * pa[h];
        }
        se[idx] = acc;
    }
    __syncthreads();

    for (int idx = tid; idx < N_*K_; idx += 256) {
        int n = idx >> 2, k = idx & 3;
        int a0 = soff[n], a1 = soff[n+1];
        float mx = -1e30f;
        for (int a = a0; a < a1; a++) mx = fmaxf(mx, se[seid[a]*K_ + k]);
        float s = 0.f;
        for (int a = a0; a < a1; a++) s += expf(se[seid[a]*K_ + k] - mx);
        float inv = 1.f / (s + 1e-16f);
        for (int a = a0; a < a1; a++) {
            int j = seid[a]*K_ + k;
            se[j] = expf(se[j] - mx) * inv;
        }
    }
    __syncthreads();

    for (int idx = tid; idx < N_*H_; idx += 256) {
        int n = idx >> 6, h = idx & 63;
        int a0 = soff[n], a1 = soff[n+1];
        float acc = 0.f;
        for (int a = a0; a < a1; a++) {
            int e = seid[a]; int s = ssrc[e];
            #pragma unroll
            for (int k2 = 0; k2 < K_; k2++)
                acc += se[e*K_ + k2] * xl[s*KHP_ + k2*H_ + h];
        }
        float v = acc * 0.25f + sb[h];
        g_seq[(size_t)g*NH_ + n*H_ + h] = fmaxf(v, 0.f);
    }
}

// ---------------- xw GEMM (proven 64x64x32 fp32) ------------------------------
#define BM 64
#define BN 64
#define BK 32
#define BMP (BM+4)
#define BNP (BN+4)
__global__ __launch_bounds__(256) void xw_gemm_kernel(
    const float* __restrict__ W_ih,
    const float* __restrict__ b_ih, const float* __restrict__ b_hh)
{
    __shared__ float As[BK][BMP];
    __shared__ float Bs[BK][BNP];
    int bn = blockIdx.x, bm = blockIdx.y;
    int tid = threadIdx.x;
    int tx = tid & 15, ty = tid >> 4;
    float acc[4][4] = {};
    const float* A0 = g_seq + (size_t)(bm*BM)*NH_;
    const float* B0 = W_ih + (size_t)(bn*BN)*NH_;
    int lr = tid >> 3;
    int lc = (tid & 7) * 4;

    for (int k0 = 0; k0 < NH_; k0 += BK) {
        #pragma unroll
        for (int half = 0; half < 2; half++) {
            int r = lr + half*32;
            float4 a4 = *(const float4*)&A0[(size_t)r*NH_ + k0 + lc];
            As[lc+0][r] = a4.x; As[lc+1][r] = a4.y;
            As[lc+2][r] = a4.z; As[lc+3][r] = a4.w;
            float4 b4 = *(const float4*)&B0[(size_t)r*NH_ + k0 + lc];
            Bs[lc+0][r] = b4.x; Bs[lc+1][r] = b4.y;
            Bs[lc+2][r] = b4.z; Bs[lc+3][r] = b4.w;
        }
        __syncthreads();
        #pragma unroll
        for (int k = 0; k < BK; k++) {
            float4 av = *(const float4*)&As[k][ty*4];
            float4 bv = *(const float4*)&Bs[k][tx*4];
            float a[4] = {av.x, av.y, av.z, av.w};
            float b[4] = {bv.x, bv.y, bv.z, bv.w};
            #pragma unroll
            for (int i = 0; i < 4; i++)
                #pragma unroll
                for (int j = 0; j < 4; j++)
                    acc[i][j] += a[i] * b[j];
        }
        __syncthreads();
    }
    #pragma unroll
    for (int i = 0; i < 4; i++) {
        int r = bm*BM + ty*4 + i;
        int c = bn*BN + tx*4;
        float4 o;
        o.x = acc[i][0] + b_ih[c+0] + b_hh[c+0];
        o.y = acc[i][1] + b_ih[c+1] + b_hh[c+1];
        o.z = acc[i][2] + b_ih[c+2] + b_hh[c+2];
        o.w = acc[i][3] + b_ih[c+3] + b_hh[c+3];
        *(float4*)&g_xw[(size_t)r*G4_ + c] = o;
    }
}

// ---------------- cluster LSTM v4: R13 dot + parallel bcast + fast tail -------
__device__ __forceinline__ float sigm_f(float x) { return 1.f / (1.f + __expf(-x)); }
__device__ __forceinline__ float tanh_f(float x) { return 1.f - 2.f / (__expf(2.f*x) + 1.f); }

__device__ __forceinline__ unsigned smem_u32(const void* p)
{
    unsigned a;
    asm("{ .reg .u64 t; cvta.to.shared.u64 t, %1; cvt.u32.u64 %0, t; }"
        : "=r"(a) : "l"(p));
    return a;
}
__device__ __forceinline__ unsigned my_cluster_rank()
{
    unsigned r;
    asm("mov.u32 %0, %%cluster_ctarank;" : "=r"(r));
    return r;
}
__device__ __forceinline__ void dsmem_store_f32(unsigned laddr, unsigned rank, float v)
{
    asm volatile(
        "{ .reg .b32 ra; mapa.shared::cluster.u32 ra, %0, %1; "
        "st.shared::cluster.f32 [ra], %2; }"
        :: "r"(laddr), "r"(rank), "f"(v) : "memory");
}

__global__ __launch_bounds__(256, 1) void lstm_cluster_kernel(const float* __restrict__ W_hh)
{
    extern __shared__ char smc[];
    __half* sw  = (__half*)smc;                  // [128][2][264] halfs
    float* hbuf = (float*)(smc + SW_BYTES);      // [2][2*HSEC] floats
    float* sval = hbuf + 2*(2*HSEC);             // 128
    float* htmp = sval + LROWS;                  // 32

    const int tid  = threadIdx.x;
    const int b    = blockIdx.x / CLU;
    const unsigned rank = my_cluster_rank();     // 0..15
    const int j0   = rank * 32;

    // load W slice as fp16 into [row][half][264] layout
    for (int idx = tid; idx < LROWS*256; idx += 256) {
        int r  = idx >> 8;            // row 0..127
        int i2 = idx & 255;           // half2 index within row (512 halfs)
        int gate = r >> 5, jr = r & 31;
        float2 wv = *(const float2*)&W_hh[(size_t)(gate*LH_ + j0 + jr)*LH_ + i2*2];
        int e  = i2*2;
        int hf = e >> 8, k = e & 255;
        *(__half2*)&sw[r*WSTR + hf*HSEC + k] = __floats2half2_rn(wv.x, wv.y);
    }
    for (int i = tid; i < 2*HSEC; i += 256) hbuf[i] = 0.f;   // h buffer 0
    __syncthreads();

    const int row = tid >> 1, hf = tid & 1;
    const int gate = row >> 5, jr = row & 31;
    const uint4* wv = (const uint4*)(sw + row*WSTR + hf*HSEC);   // 32 x 8 halfs
    const float* xp = g_xw + (size_t)(b*T_)*G4_ + gate*LH_ + j0 + jr;
    const unsigned hbuf_addr = smem_u32(hbuf);

    float xval = __ldcg(xp);
    float c = 0.f;                               // cell state (tid < 32)

    for (int t = 0; t < T_; t++) {
        const float4* hv = (const float4*)(hbuf + (t & 1)*(2*HSEC) + hf*HSEC);
        float a0 = 0.f, a1 = 0.f, a2 = 0.f, a3 = 0.f;
        #pragma unroll 4
        for (int i = 0; i < 32; i++) {
            uint4 w = wv[i];
            float4 p = hv[2*i], q = hv[2*i+1];
            float2 w0 = __half22float2(*(__half2*)&w.x);
            float2 w1 = __half22float2(*(__half2*)&w.y);
            float2 w2 = __half22float2(*(__half2*)&w.z);
            float2 w3 = __half22float2(*(__half2*)&w.w);
            a0 = fmaf(w0.x, p.x, a0); a1 = fmaf(w0.y, p.y, a1);
            a2 = fmaf(w1.x, p.z, a2); a3 = fmaf(w1.y, p.w, a3);
            a0 = fmaf(w2.x, q.x, a0); a1 = fmaf(w2.y, q.y, a1);
            a2 = fmaf(w3.x, q.z, a2); a3 = fmaf(w3.y, q.w, a3);
        }
        float s = (a0 + a1) + (a2 + a3);
        s += __shfl_xor_sync(0xffffffffu, s, 1);   // combine the two halves
        if (hf == 0) sval[row] = s + xval;
        __syncthreads();

        if (tid < 32) {
            float gi = sval[tid];
            float gf = sval[32 + tid];
            float gg = sval[64 + tid];
            float go = sval[96 + tid];
            c = sigm_f(gf)*c + sigm_f(gi)*tanh_f(gg);
            float h = sigm_f(go)*tanh_f(c);
            htmp[tid] = h;
            if (t == T_-1) g_hbuf[0][b][j0 + tid] = h;
        }
        __syncthreads();

        if (t < T_-1) {
            // parallel broadcast: warp w pushes all 32 h values to ranks 2w, 2w+1
            float v = htmp[tid & 31];
            int jg = j0 + (tid & 31);
            int hfd = jg >> 8, kd = jg & 255;
            unsigned dst = hbuf_addr + (unsigned)(((t + 1) & 1)*(2*HSEC) + hfd*HSEC + kd)*4u;
            unsigned w = (unsigned)(tid >> 5);
            dsmem_store_f32(dst, 2u*w,     v);
            dsmem_store_f32(dst, 2u*w + 1u, v);
            asm volatile("barrier.cluster.arrive.aligned;" ::: "memory");
            xval = __ldcg(xp + (size_t)(t + 1)*G4_);   // overlap with barrier skew
            asm volatile("barrier.cluster.wait.aligned;" ::: "memory");
        }
    }
    asm volatile("barrier.cluster.arrive.aligned;" ::: "memory");
    asm volatile("barrier.cluster.wait.aligned;" ::: "memory");
}

// ---------------- final fc -----------------------------------------------------
__global__ void fc_kernel(const float* __restrict__ fc_w,
                          const float* __restrict__ fc_b,
                          float* __restrict__ out)
{
    int tid = threadIdx.x;
    if (tid < B_*C_) {
        int b = tid >> 3, c = tid & 7;
        const float* h = g_hbuf[0][b];
        const float* w = fc_w + c*LH_;
        float acc = 0.f;
        for (int j = 0; j < LH_; j++) acc += h[j] * w[j];
        out[b*C_ + c] = acc + fc_b[c];
    }
}

// ---------------- launch -------------------------------------------------------
extern "C" void kernel_launch(void* const* d_in, const int* in_sizes, int n_in,
                              void* d_out, int out_size)
{
    (void)in_sizes; (void)n_in; (void)out_size;
    const float* x    = (const float*)d_in[0];
    const int*   ei   = (const int*)d_in[1];
    const float* Wl1  = (const float*)d_in[2];
    const float* Wr1  = (const float*)d_in[3];
    const float* att1 = (const float*)d_in[4];
    const float* b1   = (const float*)d_in[5];
    const float* Wl2  = (const float*)d_in[6];
    const float* Wr2  = (const float*)d_in[7];
    const float* att2 = (const float*)d_in[8];
    const float* b2   = (const float*)d_in[9];
    const float* W_ih = (const float*)d_in[10];
    const float* W_hh = (const float*)d_in[11];
    const float* b_ih = (const float*)d_in[12];
    const float* b_hh = (const float*)d_in[13];
    const float* fc_w = (const float*)d_in[14];
    const float* fc_b = (const float*)d_in[15];
    float* out = (float*)d_out;

    const size_t sm1 = (size_t)(2*N_*KHP_ + 2*F_*KH_ + 2*KH_ + N_*F_ + E_*K_) * 4
                     + (size_t)(2*E_ + (N_+1) + E_) * 4;
    const size_t sm2 = (size_t)(N_*KH_ + 2*N_*KHP_ + KH_ + H_ + E_*K_) * 4
                     + (size_t)(2*E_ + (N_+1) + E_) * 4;
    const size_t sml = SW_BYTES + (size_t)(2*(2*HSEC) + LROWS + 32) * 4;

    cudaFuncSetAttribute(gat1_kernel, cudaFuncAttributeMaxDynamicSharedMemorySize, (int)sm1);
    cudaFuncSetAttribute(gat2_kernel, cudaFuncAttributeMaxDynamicSharedMemorySize, (int)sm2);
    cudaFuncSetAttribute(lstm_cluster_kernel, cudaFuncAttributeMaxDynamicSharedMemorySize, (int)sml);
    cudaFuncSetAttribute(lstm_cluster_kernel, cudaFuncAttributeNonPortableClusterSizeAllowed, 1);

    build_csr_kernel<<<1, 64>>>(ei);
    gat1_kernel<<<G_, 256, sm1>>>(x, ei, Wl1, Wr1, att1, b1);
    gat2_kernel<<<G_, 256, sm2>>>(ei, Wl2, Wr2, att2, b2);
    dim3 gx(G4_/BN, G_/BM);
    xw_gemm_kernel<<<gx, 256>>>(W_ih, b_ih, b_hh);

    {
        cudaLaunchConfig_t cfg = {};
        cfg.gridDim  = dim3(B_*CLU, 1, 1);     // 64 CTAs = 4 clusters of 16
        cfg.blockDim = dim3(256, 1, 1);
        cfg.dynamicSmemBytes = sml;
        cfg.stream = 0;
        cudaLaunchAttribute attrs[1];
        attrs[0].id = cudaLaunchAttributeClusterDimension;
        attrs[0].val.clusterDim.x = CLU;
        attrs[0].val.clusterDim.y = 1;
        attrs[0].val.clusterDim.z = 1;
        cfg.attrs = attrs;
        cfg.numAttrs = 1;
        cudaLaunchKernelEx(&cfg, lstm_cluster_kernel, W_hh);
    }

    fc_kernel<<<1, 32>>>(fc_w, fc_b, out);
}

// round 16
// speedup vs baseline: 1.1868x; 1.1418x over previous
#include <cuda_runtime.h>
#include <cuda_fp16.h>
#include <cuda_bf16.h>
#include <math.h>
#include <mma.h>
using namespace nvcuda;

#define B_ 4
#define T_ 256
#define N_ 48
#define F_ 4
#define H_ 64
#define K_ 4
#define E_ 192
#define LH_ 512
#define C_ 8
#define G_ (B_*T_)     // 1024
#define KH_ (K_*H_)    // 256
#define KHP_ (KH_+1)
#define NH_ (N_*H_)    // 3072
#define G4_ (4*LH_)    // 2048
#define NEG_SLOPE 0.2f

#define CLU 16                 // CTAs per cluster (one cluster per batch)
#define LROWS 128              // W rows per CTA (32 j x 4 gates)
#define WSTR 528               // halfs per W row (2 sections of 264)
#define HSEC 264               // floats per h half-section
#define SW_BYTES (LROWS*WSTR*2)   // 135168

// ---------------- scratch ----------------------------------------------------
__device__ float g_h1[G_*N_*KH_];
__device__ float g_seq[G_*NH_];
__device__ float g_xw[G_*G4_];
__device__ float g_hbuf[2][B_][LH_];
__device__ int   g_coff[N_+1];
__device__ int   g_ceid[E_];

// ---------------- deterministic CSR build ------------------------------------
__global__ void build_csr_kernel(const int* __restrict__ ei)
{
    __shared__ int sdst[E_];
    __shared__ int sdeg[N_];
    __shared__ int soff[N_+1];
    int tid = threadIdx.x;
    for (int e = tid; e < E_; e += blockDim.x) sdst[e] = ei[E_ + e];
    __syncthreads();
    for (int n = tid; n < N_; n += blockDim.x) {
        int d = 0;
        for (int e = 0; e < E_; e++) d += (sdst[e] == n);
        sdeg[n] = d;
    }
    __syncthreads();
    if (tid == 0) {
        int acc = 0;
        for (int n = 0; n < N_; n++) { soff[n] = acc; acc += sdeg[n]; }
        soff[N_] = acc;
    }
    __syncthreads();
    for (int n = tid; n < N_; n += blockDim.x) {
        int p = soff[n];
        for (int e = 0; e < E_; e++) if (sdst[e] == n) g_ceid[p++] = e;
    }
    for (int n = tid; n <= N_; n += blockDim.x) g_coff[n] = soff[n];
}

// ---------------- GAT layer 1 ------------------------------------------------
__global__ __launch_bounds__(256) void gat1_kernel(
    const float* __restrict__ x, const int* __restrict__ ei,
    const float* __restrict__ Wl, const float* __restrict__ Wr,
    const float* __restrict__ att, const float* __restrict__ bias)
{
    extern __shared__ float sm[];
    float* xl   = sm;
    float* xr   = xl + N_*KHP_;
    float* wl   = xr + N_*KHP_;
    float* wr   = wl + F_*KH_;
    float* satt = wr + F_*KH_;
    float* sb   = satt + KH_;
    float* sx   = sb + KH_;
    float* se   = sx + N_*F_;
    int* ssrc = (int*)(se + E_*K_);
    int* sdst = ssrc + E_;
    int* soff = sdst + E_;
    int* seid = soff + (N_+1);

    int g = blockIdx.x;
    int tid = threadIdx.x;

    for (int i = tid; i < F_*KH_; i += 256) { wl[i] = Wl[i]; wr[i] = Wr[i]; }
    satt[tid] = att[tid];
    sb[tid] = bias[tid];
    for (int i = tid; i < N_*F_; i += 256) sx[i] = x[(size_t)g*N_*F_ + i];
    for (int i = tid; i < E_; i += 256) { ssrc[i] = ei[i]; sdst[i] = ei[E_+i]; seid[i] = g_ceid[i]; }
    for (int i = tid; i <= N_; i += 256) soff[i] = g_coff[i];
    __syncthreads();

    const int o = tid;
    for (int n = 0; n < N_; n++) {
        float al = 0.f, ar = 0.f;
        #pragma unroll
        for (int f = 0; f < F_; f++) {
            float xv = sx[n*F_ + f];
            al += xv * wl[f*KH_ + o];
            ar += xv * wr[f*KH_ + o];
        }
        xl[n*KHP_ + o] = al;
        xr[n*KHP_ + o] = ar;
    }
    __syncthreads();

    for (int idx = tid; idx < E_*K_; idx += 256) {
        int e = idx >> 2, k = idx & 3;
        const float* pl = xl + ssrc[e]*KHP_ + k*H_;
        const float* pr = xr + sdst[e]*KHP_ + k*H_;
        const float* pa = satt + k*H_;
        float acc = 0.f;
        #pragma unroll 8
        for (int h = 0; h < H_; h++) {
            float v = pl[h] + pr[h];
            v = v > 0.f ? v : NEG_SLOPE * v;
            acc += v * pa[h];
        }
        se[idx] = acc;
    }
    __syncthreads();

    for (int idx = tid; idx < N_*K_; idx += 256) {
        int n = idx >> 2, k = idx & 3;
        int a0 = soff[n], a1 = soff[n+1];
        float mx = -1e30f;
        for (int a = a0; a < a1; a++) mx = fmaxf(mx, se[seid[a]*K_ + k]);
        float s = 0.f;
        for (int a = a0; a < a1; a++) s += expf(se[seid[a]*K_ + k] - mx);
        float inv = 1.f / (s + 1e-16f);
        for (int a = a0; a < a1; a++) {
            int j = seid[a]*K_ + k;
            se[j] = expf(se[j] - mx) * inv;
        }
    }
    __syncthreads();

    int k = o >> 6;
    float* outp = g_h1 + (size_t)g*N_*KH_;
    for (int n = 0; n < N_; n++) {
        int a0 = soff[n], a1 = soff[n+1];
        float acc = 0.f;
        for (int a = a0; a < a1; a++) {
            int e = seid[a];
            acc += se[e*K_ + k] * xl[ssrc[e]*KHP_ + o];
        }
        outp[n*KH_ + o] = fmaxf(acc + sb[o], 0.f);
    }
}

// ---------------- GAT layer 2 (fused fp32, proven) ----------------------------
__global__ __launch_bounds__(256) void gat2_kernel(
    const int* __restrict__ ei,
    const float* __restrict__ Wl, const float* __restrict__ Wr,
    const float* __restrict__ att, const float* __restrict__ bias)
{
    extern __shared__ float sm[];
    float* sh_in = sm;
    float* xl    = sh_in + N_*KH_;
    float* xr    = xl + N_*KHP_;
    float* satt  = xr + N_*KHP_;
    float* sb    = satt + KH_;
    float* se    = sb + H_;
    int* ssrc = (int*)(se + E_*K_);
    int* sdst = ssrc + E_;
    int* soff = sdst + E_;
    int* seid = soff + (N_+1);

    int g = blockIdx.x;
    int tid = threadIdx.x;

    const float* h1p = g_h1 + (size_t)g*N_*KH_;
    for (int i = tid; i < N_*KH_; i += 256) sh_in[i] = h1p[i];
    satt[tid] = att[tid];
    if (tid < H_) sb[tid] = bias[tid];
    for (int i = tid; i < E_; i += 256) { ssrc[i] = ei[i]; sdst[i] = ei[E_+i]; seid[i] = g_ceid[i]; }
    for (int i = tid; i <= N_; i += 256) soff[i] = g_coff[i];
    __syncthreads();

    const int o = tid;
    {
        float acc[N_];
        #pragma unroll
        for (int n = 0; n < N_; n++) acc[n] = 0.f;
        #pragma unroll 2
        for (int i = 0; i < KH_; i++) {
            float w = Wl[i*KH_ + o];
            #pragma unroll
            for (int n = 0; n < N_; n++) acc[n] += sh_in[n*KH_ + i] * w;
        }
        #pragma unroll
        for (int n = 0; n < N_; n++) xl[n*KHP_ + o] = acc[n];
    }
    {
        float acc[N_];
        #pragma unroll
        for (int n = 0; n < N_; n++) acc[n] = 0.f;
        #pragma unroll 2
        for (int i = 0; i < KH_; i++) {
            float w = Wr[i*KH_ + o];
            #pragma unroll
            for (int n = 0; n < N_; n++) acc[n] += sh_in[n*KH_ + i] * w;
        }
        #pragma unroll
        for (int n = 0; n < N_; n++) xr[n*KHP_ + o] = acc[n];
    }
    __syncthreads();

    for (int idx = tid; idx < E_*K_; idx += 256) {
        int e = idx >> 2, k = idx & 3;
        const float* pl = xl + ssrc[e]*KHP_ + k*H_;
        const float* pr = xr + sdst[e]*KHP_ + k*H_;
        const float* pa = satt + k*H_;
        float acc = 0.f;
        #pragma unroll 8
        for (int h = 0; h < H_; h++) {
            float v = pl[h] + pr[h];
            v = v > 0.f ? v : NEG_SLOPE * v;
            acc += v * pa[h];
        }
        se[idx] = acc;
    }
    __syncthreads();

    for (int idx = tid; idx < N_*K_; idx += 256) {
        int n = idx >> 2, k = idx & 3;
        int a0 = soff[n], a1 = soff[n+1];
        float mx = -1e30f;
        for (int a = a0; a < a1; a++) mx = fmaxf(mx, se[seid[a]*K_ + k]);
        float s = 0.f;
        for (int a = a0; a < a1; a++) s += expf(se[seid[a]*K_ + k] - mx);
        float inv = 1.f / (s + 1e-16f);
        for (int a = a0; a < a1; a++) {
            int j = seid[a]*K_ + k;
            se[j] = expf(se[j] - mx) * inv;
        }
    }
    __syncthreads();

    for (int idx = tid; idx < N_*H_; idx += 256) {
        int n = idx >> 6, h = idx & 63;
        int a0 = soff[n], a1 = soff[n+1];
        float acc = 0.f;
        for (int a = a0; a < a1; a++) {
            int e = seid[a]; int s = ssrc[e];
            #pragma unroll
            for (int k2 = 0; k2 < K_; k2++)
                acc += se[e*K_ + k2] * xl[s*KHP_ + k2*H_ + h];
        }
        float v = acc * 0.25f + sb[h];
        g_seq[(size_t)g*NH_ + n*H_ + h] = fmaxf(v, 0.f);
    }
}

// ---------------- xw = seq @ W_ih^T + bias, bf16 3x WMMA (m16n16k16) ----------
// hi/lo conversion happens ONCE at tile staging; fragments load bf16 directly.
#define XLD 48   // bf16 elems per staged row (32 data + 16 pad); 96 B, 16B-mult
__global__ __launch_bounds__(128) void xw_bf16_kernel(
    const float* __restrict__ W_ih,
    const float* __restrict__ b_ih, const float* __restrict__ b_hh)
{
    __shared__ __align__(32) char smraw[4*64*XLD*2];   // 24576 B
    __nv_bfloat16* As_hi = (__nv_bfloat16*)smraw;
    __nv_bfloat16* As_lo = As_hi + 64*XLD;
    __nv_bfloat16* Bs_hi = As_lo + 64*XLD;
    __nv_bfloat16* Bs_lo = Bs_hi + 64*XLD;

    const int tid = threadIdx.x, warp = tid >> 5, lane = tid & 31;
    const int bm = blockIdx.y*64, bn = blockIdx.x*64;
    const int wm = (warp >> 1)*32, wn = (warp & 1)*32;

    wmma::fragment<wmma::accumulator,16,16,16,float> c[2][2];
    #pragma unroll
    for (int i = 0; i < 2; i++)
        #pragma unroll
        for (int j = 0; j < 2; j++) wmma::fill_fragment(c[i][j], 0.f);

    for (int k0 = 0; k0 < NH_; k0 += 32) {
        __syncthreads();
        #pragma unroll
        for (int i = 0; i < 4; i++) {
            int idx = tid + i*128;
            int m = idx >> 3, kq = (idx & 7)*4;
            float4 a = *(const float4*)&g_seq[(size_t)(bm+m)*NH_ + k0 + kq];
            __nv_bfloat16 hx = __float2bfloat16(a.x), hy = __float2bfloat16(a.y);
            __nv_bfloat16 hz = __float2bfloat16(a.z), hw = __float2bfloat16(a.w);
            As_hi[m*XLD+kq+0] = hx; As_hi[m*XLD+kq+1] = hy;
            As_hi[m*XLD+kq+2] = hz; As_hi[m*XLD+kq+3] = hw;
            As_lo[m*XLD+kq+0] = __float2bfloat16(a.x - __bfloat162float(hx));
            As_lo[m*XLD+kq+1] = __float2bfloat16(a.y - __bfloat162float(hy));
            As_lo[m*XLD+kq+2] = __float2bfloat16(a.z - __bfloat162float(hz));
            As_lo[m*XLD+kq+3] = __float2bfloat16(a.w - __bfloat162float(hw));
            float4 b = *(const float4*)&W_ih[(size_t)(bn+m)*NH_ + k0 + kq];
            __nv_bfloat16 gx = __float2bfloat16(b.x), gy = __float2bfloat16(b.y);
            __nv_bfloat16 gz = __float2bfloat16(b.z), gw = __float2bfloat16(b.w);
            Bs_hi[m*XLD+kq+0] = gx; Bs_hi[m*XLD+kq+1] = gy;
            Bs_hi[m*XLD+kq+2] = gz; Bs_hi[m*XLD+kq+3] = gw;
            Bs_lo[m*XLD+kq+0] = __float2bfloat16(b.x - __bfloat162float(gx));
            Bs_lo[m*XLD+kq+1] = __float2bfloat16(b.y - __bfloat162float(gy));
            Bs_lo[m*XLD+kq+2] = __float2bfloat16(b.z - __bfloat162float(gz));
            Bs_lo[m*XLD+kq+3] = __float2bfloat16(b.w - __bfloat162float(gw));
        }
        __syncthreads();

        #pragma unroll
        for (int ks = 0; ks < 32; ks += 16) {
            wmma::fragment<wmma::matrix_a,16,16,16,__nv_bfloat16,wmma::row_major> ah[2], al[2];
            wmma::fragment<wmma::matrix_b,16,16,16,__nv_bfloat16,wmma::col_major> bh[2], bl[2];
            #pragma unroll
            for (int i = 0; i < 2; i++) {
                wmma::load_matrix_sync(ah[i], &As_hi[(wm + i*16)*XLD + ks], XLD);
                wmma::load_matrix_sync(al[i], &As_lo[(wm + i*16)*XLD + ks], XLD);
                wmma::load_matrix_sync(bh[i], &Bs_hi[(wn + i*16)*XLD + ks], XLD);
                wmma::load_matrix_sync(bl[i], &Bs_lo[(wn + i*16)*XLD + ks], XLD);
            }
            #pragma unroll
            for (int i = 0; i < 2; i++)
                #pragma unroll
                for (int j = 0; j < 2; j++) {
                    wmma::mma_sync(c[i][j], ah[i], bh[j], c[i][j]);  // hi*hi
                    wmma::mma_sync(c[i][j], al[i], bh[j], c[i][j]);  // lo*hi
                    wmma::mma_sync(c[i][j], ah[i], bl[j], c[i][j]);  // hi*lo
                }
        }
    }

    // epilogue: stage through smem (reuse), add bias, vectorized store
    __syncthreads();
    float* ct = (float*)smraw + warp*1152;       // 32x36 floats per warp
    #pragma unroll
    for (int i = 0; i < 2; i++)
        #pragma unroll
        for (int j = 0; j < 2; j++)
            wmma::store_matrix_sync(&ct[(i*16)*36 + j*16], c[i][j], 36, wmma::mem_row_major);
    __syncwarp();
    for (int q = lane; q < 256; q += 32) {
        int r = q >> 3, cq = (q & 7)*4;
        float4 v = *(const float4*)&ct[r*36 + cq];
        int gr = bm + wm + r, gc = bn + wn + cq;
        v.x += b_ih[gc+0] + b_hh[gc+0];
        v.y += b_ih[gc+1] + b_hh[gc+1];
        v.z += b_ih[gc+2] + b_hh[gc+2];
        v.w += b_ih[gc+3] + b_hh[gc+3];
        *(float4*)&g_xw[(size_t)gr*G4_ + gc] = v;
    }
}

// ---------------- cluster LSTM (exact R13 winner) -----------------------------
__device__ __forceinline__ float sigm(float x) { return 1.f / (1.f + expf(-x)); }

__device__ __forceinline__ unsigned smem_u32(const void* p)
{
    unsigned a;
    asm("{ .reg .u64 t; cvta.to.shared.u64 t, %1; cvt.u32.u64 %0, t; }"
        : "=r"(a) : "l"(p));
    return a;
}
__device__ __forceinline__ unsigned my_cluster_rank()
{
    unsigned r;
    asm("mov.u32 %0, %%cluster_ctarank;" : "=r"(r));
    return r;
}
__device__ __forceinline__ void dsmem_store_f32(unsigned laddr, unsigned rank, float v)
{
    asm volatile(
        "{ .reg .b32 ra; mapa.shared::cluster.u32 ra, %0, %1; "
        "st.shared::cluster.f32 [ra], %2; }"
        :: "r"(laddr), "r"(rank), "f"(v) : "memory");
}

__global__ __launch_bounds__(256, 1) void lstm_cluster_kernel(const float* __restrict__ W_hh)
{
    extern __shared__ char smc[];
    __half* sw  = (__half*)smc;                  // [128][2][264] halfs
    float* hbuf = (float*)(smc + SW_BYTES);      // [2][2*HSEC] floats
    float* sval = hbuf + 2*(2*HSEC);             // 128

    const int tid  = threadIdx.x;
    const int b    = blockIdx.x / CLU;
    const unsigned rank = my_cluster_rank();     // 0..15
    const int j0   = rank * 32;

    for (int idx = tid; idx < LROWS*256; idx += 256) {
        int r  = idx >> 8;
        int i2 = idx & 255;
        int gate = r >> 5, jr = r & 31;
        float2 wv = *(const float2*)&W_hh[(size_t)(gate*LH_ + j0 + jr)*LH_ + i2*2];
        int e  = i2*2;
        int hf = e >> 8, k = e & 255;
        *(__half2*)&sw[r*WSTR + hf*HSEC + k] = __floats2half2_rn(wv.x, wv.y);
    }
    for (int i = tid; i < 2*HSEC; i += 256) hbuf[i] = 0.f;
    __syncthreads();

    const int row = tid >> 1, hf = tid & 1;
    const int gate = row >> 5, jr = row & 31;
    const uint4* wv = (const uint4*)(sw + row*WSTR + hf*HSEC);
    const float* xp = g_xw + (size_t)(b*T_)*G4_ + gate*LH_ + j0 + jr;
    const unsigned hbuf_addr = smem_u32(hbuf);

    float xval = __ldcg(xp);
    float c = 0.f;

    for (int t = 0; t < T_; t++) {
        const float4* hv = (const float4*)(hbuf + (t & 1)*(2*HSEC) + hf*HSEC);
        float a0 = 0.f, a1 = 0.f, a2 = 0.f, a3 = 0.f;
        #pragma unroll 4
        for (int i = 0; i < 32; i++) {
            uint4 w = wv[i];
            float4 p = hv[2*i], q = hv[2*i+1];
            float2 w0 = __half22float2(*(__half2*)&w.x);
            float2 w1 = __half22float2(*(__half2*)&w.y);
            float2 w2 = __half22float2(*(__half2*)&w.z);
            float2 w3 = __half22float2(*(__half2*)&w.w);
            a0 = fmaf(w0.x, p.x, a0); a1 = fmaf(w0.y, p.y, a1);
            a2 = fmaf(w1.x, p.z, a2); a3 = fmaf(w1.y, p.w, a3);
            a0 = fmaf(w2.x, q.x, a0); a1 = fmaf(w2.y, q.y, a1);
            a2 = fmaf(w3.x, q.z, a2); a3 = fmaf(w3.y, q.w, a3);
        }
        float s = (a0 + a1) + (a2 + a3);
        s += __shfl_xor_sync(0xffffffffu, s, 1);
        if (hf == 0) sval[row] = s + xval;
        __syncthreads();

        if (tid < 32) {
            float gi = sval[tid];
            float gf = sval[32 + tid];
            float gg = sval[64 + tid];
            float go = sval[96 + tid];
            c = sigm(gf)*c + sigm(gi)*tanhf(gg);
            float h = sigm(go)*tanhf(c);
            if (t == T_-1) {
                g_hbuf[0][b][j0 + tid] = h;
            } else {
                int jg = j0 + tid;
                int hfd = jg >> 8, kd = jg & 255;
                unsigned dst = hbuf_addr + (unsigned)(((t + 1) & 1)*(2*HSEC) + hfd*HSEC + kd)*4u;
                #pragma unroll
                for (int q = 0; q < CLU; q++)
                    dsmem_store_f32(dst, (unsigned)q, h);
            }
        }
        if (t < T_-1) {
            xval = __ldcg(xp + (size_t)(t + 1)*G4_);
            asm volatile("barrier.cluster.arrive.aligned;" ::: "memory");
            asm volatile("barrier.cluster.wait.aligned;" ::: "memory");
        }
    }
    asm volatile("barrier.cluster.arrive.aligned;" ::: "memory");
    asm volatile("barrier.cluster.wait.aligned;" ::: "memory");
}

// ---------------- final fc -----------------------------------------------------
__global__ void fc_kernel(const float* __restrict__ fc_w,
                          const float* __restrict__ fc_b,
                          float* __restrict__ out)
{
    int tid = threadIdx.x;
    if (tid < B_*C_) {
        int b = tid >> 3, c = tid & 7;
        const float* h = g_hbuf[0][b];
        const float* w = fc_w + c*LH_;
        float acc = 0.f;
        for (int j = 0; j < LH_; j++) acc += h[j] * w[j];
        out[b*C_ + c] = acc + fc_b[c];
    }
}

// ---------------- launch -------------------------------------------------------
extern "C" void kernel_launch(void* const* d_in, const int* in_sizes, int n_in,
                              void* d_out, int out_size)
{
    (void)in_sizes; (void)n_in; (void)out_size;
    const float* x    = (const float*)d_in[0];
    const int*   ei   = (const int*)d_in[1];
    const float* Wl1  = (const float*)d_in[2];
    const float* Wr1  = (const float*)d_in[3];
    const float* att1 = (const float*)d_in[4];
    const float* b1   = (const float*)d_in[5];
    const float* Wl2  = (const float*)d_in[6];
    const float* Wr2  = (const float*)d_in[7];
    const float* att2 = (const float*)d_in[8];
    const float* b2   = (const float*)d_in[9];
    const float* W_ih = (const float*)d_in[10];
    const float* W_hh = (const float*)d_in[11];
    const float* b_ih = (const float*)d_in[12];
    const float* b_hh = (const float*)d_in[13];
    const float* fc_w = (const float*)d_in[14];
    const float* fc_b = (const float*)d_in[15];
    float* out = (float*)d_out;

    const size_t sm1 = (size_t)(2*N_*KHP_ + 2*F_*KH_ + 2*KH_ + N_*F_ + E_*K_) * 4
                     + (size_t)(2*E_ + (N_+1) + E_) * 4;
    const size_t sm2 = (size_t)(N_*KH_ + 2*N_*KHP_ + KH_ + H_ + E_*K_) * 4
                     + (size_t)(2*E_ + (N_+1) + E_) * 4;
    const size_t sml = SW_BYTES + (size_t)(2*(2*HSEC) + LROWS) * 4;

    cudaFuncSetAttribute(gat1_kernel, cudaFuncAttributeMaxDynamicSharedMemorySize, (int)sm1);
    cudaFuncSetAttribute(gat2_kernel, cudaFuncAttributeMaxDynamicSharedMemorySize, (int)sm2);
    cudaFuncSetAttribute(lstm_cluster_kernel, cudaFuncAttributeMaxDynamicSharedMemorySize, (int)sml);
    cudaFuncSetAttribute(lstm_cluster_kernel, cudaFuncAttributeNonPortableClusterSizeAllowed, 1);

    build_csr_kernel<<<1, 64>>>(ei);
    gat1_kernel<<<G_, 256, sm1>>>(x, ei, Wl1, Wr1, att1, b1);
    gat2_kernel<<<G_, 256, sm2>>>(ei, Wl2, Wr2, att2, b2);
    xw_bf16_kernel<<<dim3(G4_/64, G_/64), 128>>>(W_ih, b_ih, b_hh);

    {
        cudaLaunchConfig_t cfg = {};
        cfg.gridDim  = dim3(B_*CLU, 1, 1);     // 64 CTAs = 4 clusters of 16
        cfg.blockDim = dim3(256, 1, 1);
        cfg.dynamicSmemBytes = sml;
        cfg.stream = 0;
        cudaLaunchAttribute attrs[1];
        attrs[0].id = cudaLaunchAttributeClusterDimension;
        attrs[0].val.clusterDim.x = CLU;
        attrs[0].val.clusterDim.y = 1;
        attrs[0].val.clusterDim.z = 1;
        cfg.attrs = attrs;
        cfg.numAttrs = 1;
        cudaLaunchKernelEx(&cfg, lstm_cluster_kernel, W_hh);
    }

    fc_kernel<<<1, 32>>>(fc_w, fc_b, out);
}

// round 17
// speedup vs baseline: 1.6527x; 1.3926x over previous
#include <cuda_runtime.h>
#include <cuda_fp16.h>
#include <cuda_bf16.h>
#include <math.h>
#include <mma.h>
using namespace nvcuda;

#define B_ 4
#define T_ 256
#define N_ 48
#define F_ 4
#define H_ 64
#define K_ 4
#define E_ 192
#define LH_ 512
#define C_ 8
#define G_ (B_*T_)     // 1024
#define KH_ (K_*H_)    // 256
#define KHP_ (KH_+1)
#define NH_ (N_*H_)    // 3072
#define G4_ (4*LH_)    // 2048
#define NEG_SLOPE 0.2f

#define CLU 16                 // CTAs per cluster (one cluster per batch)
#define LROWS 128              // W rows per CTA (32 j x 4 gates)
#define WSTR 528               // halfs per W row (2 sections of 264)
#define HSEC 264               // floats per h half-section
#define SW_BYTES (LROWS*WSTR*2)   // 135168

// gat2 tiling
#define HLD 272   // bf16 k-stride for staged h1 rows (256 + 16)
#define WLD 264   // bf16 n-stride for staged W tiles (256 + 8)
#define XP  260   // f32 row stride for xl/xr (multiple of 4 for wmma store)

// ---------------- scratch ----------------------------------------------------
__device__ float g_h1[G_*N_*KH_];
__device__ float g_seq[G_*NH_];
__device__ float g_xw[G_*G4_];
__device__ float g_hbuf[2][B_][LH_];
__device__ int   g_coff[N_+1];
__device__ int   g_ceid[E_];

// ---------------- deterministic CSR build ------------------------------------
__global__ void build_csr_kernel(const int* __restrict__ ei)
{
    __shared__ int sdst[E_];
    __shared__ int sdeg[N_];
    __shared__ int soff[N_+1];
    int tid = threadIdx.x;
    for (int e = tid; e < E_; e += blockDim.x) sdst[e] = ei[E_ + e];
    __syncthreads();
    for (int n = tid; n < N_; n += blockDim.x) {
        int d = 0;
        for (int e = 0; e < E_; e++) d += (sdst[e] == n);
        sdeg[n] = d;
    }
    __syncthreads();
    if (tid == 0) {
        int acc = 0;
        for (int n = 0; n < N_; n++) { soff[n] = acc; acc += sdeg[n]; }
        soff[N_] = acc;
    }
    __syncthreads();
    for (int n = tid; n < N_; n += blockDim.x) {
        int p = soff[n];
        for (int e = 0; e < E_; e++) if (sdst[e] == n) g_ceid[p++] = e;
    }
    for (int n = tid; n <= N_; n += blockDim.x) g_coff[n] = soff[n];
}

// ---------------- GAT layer 1 ------------------------------------------------
__global__ __launch_bounds__(256) void gat1_kernel(
    const float* __restrict__ x, const int* __restrict__ ei,
    const float* __restrict__ Wl, const float* __restrict__ Wr,
    const float* __restrict__ att, const float* __restrict__ bias)
{
    extern __shared__ float sm[];
    float* xl   = sm;
    float* xr   = xl + N_*KHP_;
    float* wl   = xr + N_*KHP_;
    float* wr   = wl + F_*KH_;
    float* satt = wr + F_*KH_;
    float* sb   = satt + KH_;
    float* sx   = sb + KH_;
    float* se   = sx + N_*F_;
    int* ssrc = (int*)(se + E_*K_);
    int* sdst = ssrc + E_;
    int* soff = sdst + E_;
    int* seid = soff + (N_+1);

    int g = blockIdx.x;
    int tid = threadIdx.x;

    for (int i = tid; i < F_*KH_; i += 256) { wl[i] = Wl[i]; wr[i] = Wr[i]; }
    satt[tid] = att[tid];
    sb[tid] = bias[tid];
    for (int i = tid; i < N_*F_; i += 256) sx[i] = x[(size_t)g*N_*F_ + i];
    for (int i = tid; i < E_; i += 256) { ssrc[i] = ei[i]; sdst[i] = ei[E_+i]; seid[i] = g_ceid[i]; }
    for (int i = tid; i <= N_; i += 256) soff[i] = g_coff[i];
    __syncthreads();

    const int o = tid;
    for (int n = 0; n < N_; n++) {
        float al = 0.f, ar = 0.f;
        #pragma unroll
        for (int f = 0; f < F_; f++) {
            float xv = sx[n*F_ + f];
            al += xv * wl[f*KH_ + o];
            ar += xv * wr[f*KH_ + o];
        }
        xl[n*KHP_ + o] = al;
        xr[n*KHP_ + o] = ar;
    }
    __syncthreads();

    for (int idx = tid; idx < E_*K_; idx += 256) {
        int e = idx >> 2, k = idx & 3;
        const float* pl = xl + ssrc[e]*KHP_ + k*H_;
        const float* pr = xr + sdst[e]*KHP_ + k*H_;
        const float* pa = satt + k*H_;
        float acc = 0.f;
        #pragma unroll 8
        for (int h = 0; h < H_; h++) {
            float v = pl[h] + pr[h];
            v = v > 0.f ? v : NEG_SLOPE * v;
            acc += v * pa[h];
        }
        se[idx] = acc;
    }
    __syncthreads();

    for (int idx = tid; idx < N_*K_; idx += 256) {
        int n = idx >> 2, k = idx & 3;
        int a0 = soff[n], a1 = soff[n+1];
        float mx = -1e30f;
        for (int a = a0; a < a1; a++) mx = fmaxf(mx, se[seid[a]*K_ + k]);
        float s = 0.f;
        for (int a = a0; a < a1; a++) s += expf(se[seid[a]*K_ + k] - mx);
        float inv = 1.f / (s + 1e-16f);
        for (int a = a0; a < a1; a++) {
            int j = seid[a]*K_ + k;
            se[j] = expf(se[j] - mx) * inv;
        }
    }
    __syncthreads();

    int k = o >> 6;
    float* outp = g_h1 + (size_t)g*N_*KH_;
    for (int n = 0; n < N_; n++) {
        int a0 = soff[n], a1 = soff[n+1];
        float acc = 0.f;
        for (int a = a0; a < a1; a++) {
            int e = seid[a];
            acc += se[e*K_ + k] * xl[ssrc[e]*KHP_ + o];
        }
        outp[n*KH_ + o] = fmaxf(acc + sb[o], 0.f);
    }
}

// ---------------- GAT layer 2: fused, bf16-3x WMMA GEMM + fp32 attention ------
__global__ __launch_bounds__(256) void gat2_kernel(
    const int* __restrict__ ei,
    const float* __restrict__ Wl, const float* __restrict__ Wr,
    const float* __restrict__ att, const float* __restrict__ bias)
{
    extern __shared__ char smraw[];
    __nv_bfloat16* h_hi = (__nv_bfloat16*)smraw;     // [48][HLD]
    __nv_bfloat16* h_lo = h_hi + N_*HLD;
    __nv_bfloat16* w_hi = h_lo + N_*HLD;             // [32][WLD]
    __nv_bfloat16* w_lo = w_hi + 32*WLD;
    float* xl   = (float*)(w_lo + 32*WLD);           // [48][XP]
    float* xr   = xl + N_*XP;
    float* satt = xr + N_*XP;                        // 256
    float* sb   = satt + KH_;                        // 64
    float* se   = sb + H_;                           // 768
    int* ssrc = (int*)(se + E_*K_);
    int* sdst = ssrc + E_;
    int* soff = sdst + E_;
    int* seid = soff + (N_+1);

    int g = blockIdx.x;
    int tid = threadIdx.x;
    const int warp = tid >> 5;

    // stage h1 (48x256) as bf16 hi/lo
    const float* h1p = g_h1 + (size_t)g*N_*KH_;
    for (int idx = tid; idx < N_*64; idx += 256) {
        int n = idx >> 6, kq = (idx & 63)*4;
        float4 v = *(const float4*)&h1p[n*KH_ + kq];
        __nv_bfloat16 hx = __float2bfloat16(v.x), hy = __float2bfloat16(v.y);
        __nv_bfloat16 hz = __float2bfloat16(v.z), hw = __float2bfloat16(v.w);
        h_hi[n*HLD+kq+0] = hx; h_hi[n*HLD+kq+1] = hy;
        h_hi[n*HLD+kq+2] = hz; h_hi[n*HLD+kq+3] = hw;
        h_lo[n*HLD+kq+0] = __float2bfloat16(v.x - __bfloat162float(hx));
        h_lo[n*HLD+kq+1] = __float2bfloat16(v.y - __bfloat162float(hy));
        h_lo[n*HLD+kq+2] = __float2bfloat16(v.z - __bfloat162float(hz));
        h_lo[n*HLD+kq+3] = __float2bfloat16(v.w - __bfloat162float(hw));
    }
    satt[tid] = att[tid];
    if (tid < H_) sb[tid] = bias[tid];
    for (int i = tid; i < E_; i += 256) { ssrc[i] = ei[i]; sdst[i] = ei[E_+i]; seid[i] = g_ceid[i]; }
    for (int i = tid; i <= N_; i += 256) soff[i] = g_coff[i];
    __syncthreads();

    // GEMM passes: W in {Wl -> xl, Wr -> xr}
    #pragma unroll 1
    for (int pass = 0; pass < 2; pass++) {
        const float* Wm = pass ? Wr : Wl;
        float* xout = pass ? xr : xl;

        wmma::fragment<wmma::accumulator,16,16,16,float> acc[3][2];
        #pragma unroll
        for (int m = 0; m < 3; m++)
            #pragma unroll
            for (int j = 0; j < 2; j++) wmma::fill_fragment(acc[m][j], 0.f);

        for (int k0 = 0; k0 < KH_; k0 += 32) {
            __syncthreads();   // previous tile fully consumed
            for (int idx = tid; idx < 32*64; idx += 256) {
                int kr = idx >> 6, nc = (idx & 63)*4;
                float4 v = *(const float4*)&Wm[(size_t)(k0+kr)*KH_ + nc];
                __nv_bfloat16 hx = __float2bfloat16(v.x), hy = __float2bfloat16(v.y);
                __nv_bfloat16 hz = __float2bfloat16(v.z), hw = __float2bfloat16(v.w);
                w_hi[kr*WLD+nc+0] = hx; w_hi[kr*WLD+nc+1] = hy;
                w_hi[kr*WLD+nc+2] = hz; w_hi[kr*WLD+nc+3] = hw;
                w_lo[kr*WLD+nc+0] = __float2bfloat16(v.x - __bfloat162float(hx));
                w_lo[kr*WLD+nc+1] = __float2bfloat16(v.y - __bfloat162float(hy));
                w_lo[kr*WLD+nc+2] = __float2bfloat16(v.z - __bfloat162float(hz));
                w_lo[kr*WLD+nc+3] = __float2bfloat16(v.w - __bfloat162float(hw));
            }
            __syncthreads();

            #pragma unroll
            for (int kk = 0; kk < 32; kk += 16) {
                wmma::fragment<wmma::matrix_a,16,16,16,__nv_bfloat16,wmma::row_major> ah[3], al[3];
                wmma::fragment<wmma::matrix_b,16,16,16,__nv_bfloat16,wmma::row_major> bh[2], bl[2];
                #pragma unroll
                for (int m = 0; m < 3; m++) {
                    wmma::load_matrix_sync(ah[m], &h_hi[(m*16)*HLD + k0 + kk], HLD);
                    wmma::load_matrix_sync(al[m], &h_lo[(m*16)*HLD + k0 + kk], HLD);
                }
                #pragma unroll
                for (int j = 0; j < 2; j++) {
                    wmma::load_matrix_sync(bh[j], &w_hi[kk*WLD + warp*32 + j*16], WLD);
                    wmma::load_matrix_sync(bl[j], &w_lo[kk*WLD + warp*32 + j*16], WLD);
                }
                #pragma unroll
                for (int m = 0; m < 3; m++)
                    #pragma unroll
                    for (int j = 0; j < 2; j++) {
                        wmma::mma_sync(acc[m][j], ah[m], bh[j], acc[m][j]);
                        wmma::mma_sync(acc[m][j], al[m], bh[j], acc[m][j]);
                        wmma::mma_sync(acc[m][j], ah[m], bl[j], acc[m][j]);
                    }
            }
        }
        #pragma unroll
        for (int m = 0; m < 3; m++)
            #pragma unroll
            for (int j = 0; j < 2; j++)
                wmma::store_matrix_sync(&xout[(m*16)*XP + warp*32 + j*16],
                                        acc[m][j], XP, wmma::mem_row_major);
    }
    __syncthreads();

    // attention (identical to proven fp32 version, stride XP)
    for (int idx = tid; idx < E_*K_; idx += 256) {
        int e = idx >> 2, k = idx & 3;
        const float* pl = xl + ssrc[e]*XP + k*H_;
        const float* pr = xr + sdst[e]*XP + k*H_;
        const float* pa = satt + k*H_;
        float acc = 0.f;
        #pragma unroll 8
        for (int h = 0; h < H_; h++) {
            float v = pl[h] + pr[h];
            v = v > 0.f ? v : NEG_SLOPE * v;
            acc += v * pa[h];
        }
        se[idx] = acc;
    }
    __syncthreads();

    for (int idx = tid; idx < N_*K_; idx += 256) {
        int n = idx >> 2, k = idx & 3;
        int a0 = soff[n], a1 = soff[n+1];
        float mx = -1e30f;
        for (int a = a0; a < a1; a++) mx = fmaxf(mx, se[seid[a]*K_ + k]);
        float s = 0.f;
        for (int a = a0; a < a1; a++) s += expf(se[seid[a]*K_ + k] - mx);
        float inv = 1.f / (s + 1e-16f);
        for (int a = a0; a < a1; a++) {
            int j = seid[a]*K_ + k;
            se[j] = expf(se[j] - mx) * inv;
        }
    }
    __syncthreads();

    for (int idx = tid; idx < N_*H_; idx += 256) {
        int n = idx >> 6, h = idx & 63;
        int a0 = soff[n], a1 = soff[n+1];
        float acc = 0.f;
        for (int a = a0; a < a1; a++) {
            int e = seid[a]; int s = ssrc[e];
            #pragma unroll
            for (int k2 = 0; k2 < K_; k2++)
                acc += se[e*K_ + k2] * xl[s*XP + k2*H_ + h];
        }
        float v = acc * 0.25f + sb[h];
        g_seq[(size_t)g*NH_ + n*H_ + h] = fmaxf(v, 0.f);
    }
}

// ---------------- xw = seq @ W_ih^T + bias, bf16 3x WMMA (R16 winner) ---------
#define XLD 48
__global__ __launch_bounds__(128) void xw_bf16_kernel(
    const float* __restrict__ W_ih,
    const float* __restrict__ b_ih, const float* __restrict__ b_hh)
{
    __shared__ __align__(32) char smraw[4*64*XLD*2];
    __nv_bfloat16* As_hi = (__nv_bfloat16*)smraw;
    __nv_bfloat16* As_lo = As_hi + 64*XLD;
    __nv_bfloat16* Bs_hi = As_lo + 64*XLD;
    __nv_bfloat16* Bs_lo = Bs_hi + 64*XLD;

    const int tid = threadIdx.x, warp = tid >> 5, lane = tid & 31;
    const int bm = blockIdx.y*64, bn = blockIdx.x*64;
    const int wm = (warp >> 1)*32, wn = (warp & 1)*32;

    wmma::fragment<wmma::accumulator,16,16,16,float> c[2][2];
    #pragma unroll
    for (int i = 0; i < 2; i++)
        #pragma unroll
        for (int j = 0; j < 2; j++) wmma::fill_fragment(c[i][j], 0.f);

    for (int k0 = 0; k0 < NH_; k0 += 32) {
        __syncthreads();
        #pragma unroll
        for (int i = 0; i < 4; i++) {
            int idx = tid + i*128;
            int m = idx >> 3, kq = (idx & 7)*4;
            float4 a = *(const float4*)&g_seq[(size_t)(bm+m)*NH_ + k0 + kq];
            __nv_bfloat16 hx = __float2bfloat16(a.x), hy = __float2bfloat16(a.y);
            __nv_bfloat16 hz = __float2bfloat16(a.z), hw = __float2bfloat16(a.w);
            As_hi[m*XLD+kq+0] = hx; As_hi[m*XLD+kq+1] = hy;
            As_hi[m*XLD+kq+2] = hz; As_hi[m*XLD+kq+3] = hw;
            As_lo[m*XLD+kq+0] = __float2bfloat16(a.x - __bfloat162float(hx));
            As_lo[m*XLD+kq+1] = __float2bfloat16(a.y - __bfloat162float(hy));
            As_lo[m*XLD+kq+2] = __float2bfloat16(a.z - __bfloat162float(hz));
            As_lo[m*XLD+kq+3] = __float2bfloat16(a.w - __bfloat162float(hw));
            float4 b = *(const float4*)&W_ih[(size_t)(bn+m)*NH_ + k0 + kq];
            __nv_bfloat16 gx = __float2bfloat16(b.x), gy = __float2bfloat16(b.y);
            __nv_bfloat16 gz = __float2bfloat16(b.z), gw = __float2bfloat16(b.w);
            Bs_hi[m*XLD+kq+0] = gx; Bs_hi[m*XLD+kq+1] = gy;
            Bs_hi[m*XLD+kq+2] = gz; Bs_hi[m*XLD+kq+3] = gw;
            Bs_lo[m*XLD+kq+0] = __float2bfloat16(b.x - __bfloat162float(gx));
            Bs_lo[m*XLD+kq+1] = __float2bfloat16(b.y - __bfloat162float(gy));
            Bs_lo[m*XLD+kq+2] = __float2bfloat16(b.z - __bfloat162float(gz));
            Bs_lo[m*XLD+kq+3] = __float2bfloat16(b.w - __bfloat162float(gw));
        }
        __syncthreads();

        #pragma unroll
        for (int ks = 0; ks < 32; ks += 16) {
            wmma::fragment<wmma::matrix_a,16,16,16,__nv_bfloat16,wmma::row_major> ah[2], al[2];
            wmma::fragment<wmma::matrix_b,16,16,16,__nv_bfloat16,wmma::col_major> bh[2], bl[2];
            #pragma unroll
            for (int i = 0; i < 2; i++) {
                wmma::load_matrix_sync(ah[i], &As_hi[(wm + i*16)*XLD + ks], XLD);
                wmma::load_matrix_sync(al[i], &As_lo[(wm + i*16)*XLD + ks], XLD);
                wmma::load_matrix_sync(bh[i], &Bs_hi[(wn + i*16)*XLD + ks], XLD);
                wmma::load_matrix_sync(bl[i], &Bs_lo[(wn + i*16)*XLD + ks], XLD);
            }
            #pragma unroll
            for (int i = 0; i < 2; i++)
                #pragma unroll
                for (int j = 0; j < 2; j++) {
                    wmma::mma_sync(c[i][j], ah[i], bh[j], c[i][j]);
                    wmma::mma_sync(c[i][j], al[i], bh[j], c[i][j]);
                    wmma::mma_sync(c[i][j], ah[i], bl[j], c[i][j]);
                }
        }
    }

    __syncthreads();
    float* ct = (float*)smraw + warp*1152;
    #pragma unroll
    for (int i = 0; i < 2; i++)
        #pragma unroll
        for (int j = 0; j < 2; j++)
            wmma::store_matrix_sync(&ct[(i*16)*36 + j*16], c[i][j], 36, wmma::mem_row_major);
    __syncwarp();
    for (int q = lane; q < 256; q += 32) {
        int r = q >> 3, cq = (q & 7)*4;
        float4 v = *(const float4*)&ct[r*36 + cq];
        int gr = bm + wm + r, gc = bn + wn + cq;
        v.x += b_ih[gc+0] + b_hh[gc+0];
        v.y += b_ih[gc+1] + b_hh[gc+1];
        v.z += b_ih[gc+2] + b_hh[gc+2];
        v.w += b_ih[gc+3] + b_hh[gc+3];
        *(float4*)&g_xw[(size_t)gr*G4_ + gc] = v;
    }
}

// ---------------- cluster LSTM (exact R13 winner) -----------------------------
__device__ __forceinline__ float sigm(float x) { return 1.f / (1.f + expf(-x)); }

__device__ __forceinline__ unsigned smem_u32(const void* p)
{
    unsigned a;
    asm("{ .reg .u64 t; cvta.to.shared.u64 t, %1; cvt.u32.u64 %0, t; }"
        : "=r"(a) : "l"(p));
    return a;
}
__device__ __forceinline__ unsigned my_cluster_rank()
{
    unsigned r;
    asm("mov.u32 %0, %%cluster_ctarank;" : "=r"(r));
    return r;
}
__device__ __forceinline__ void dsmem_store_f32(unsigned laddr, unsigned rank, float v)
{
    asm volatile(
        "{ .reg .b32 ra; mapa.shared::cluster.u32 ra, %0, %1; "
        "st.shared::cluster.f32 [ra], %2; }"
        :: "r"(laddr), "r"(rank), "f"(v) : "memory");
}

__global__ __launch_bounds__(256, 1) void lstm_cluster_kernel(const float* __restrict__ W_hh)
{
    extern __shared__ char smc[];
    __half* sw  = (__half*)smc;                  // [128][2][264] halfs
    float* hbuf = (float*)(smc + SW_BYTES);      // [2][2*HSEC] floats
    float* sval = hbuf + 2*(2*HSEC);             // 128

    const int tid  = threadIdx.x;
    const int b    = blockIdx.x / CLU;
    const unsigned rank = my_cluster_rank();     // 0..15
    const int j0   = rank * 32;

    for (int idx = tid; idx < LROWS*256; idx += 256) {
        int r  = idx >> 8;
        int i2 = idx & 255;
        int gate = r >> 5, jr = r & 31;
        float2 wv = *(const float2*)&W_hh[(size_t)(gate*LH_ + j0 + jr)*LH_ + i2*2];
        int e  = i2*2;
        int hf = e >> 8, k = e & 255;
        *(__half2*)&sw[r*WSTR + hf*HSEC + k] = __floats2half2_rn(wv.x, wv.y);
    }
    for (int i = tid; i < 2*HSEC; i += 256) hbuf[i] = 0.f;
    __syncthreads();

    const int row = tid >> 1, hf = tid & 1;
    const int gate = row >> 5, jr = row & 31;
    const uint4* wv = (const uint4*)(sw + row*WSTR + hf*HSEC);
    const float* xp = g_xw + (size_t)(b*T_)*G4_ + gate*LH_ + j0 + jr;
    const unsigned hbuf_addr = smem_u32(hbuf);

    float xval = __ldcg(xp);
    float c = 0.f;

    for (int t = 0; t < T_; t++) {
        const float4* hv = (const float4*)(hbuf + (t & 1)*(2*HSEC) + hf*HSEC);
        float a0 = 0.f, a1 = 0.f, a2 = 0.f, a3 = 0.f;
        #pragma unroll 4
        for (int i = 0; i < 32; i++) {
            uint4 w = wv[i];
            float4 p = hv[2*i], q = hv[2*i+1];
            float2 w0 = __half22float2(*(__half2*)&w.x);
            float2 w1 = __half22float2(*(__half2*)&w.y);
            float2 w2 = __half22float2(*(__half2*)&w.z);
            float2 w3 = __half22float2(*(__half2*)&w.w);
            a0 = fmaf(w0.x, p.x, a0); a1 = fmaf(w0.y, p.y, a1);
            a2 = fmaf(w1.x, p.z, a2); a3 = fmaf(w1.y, p.w, a3);
            a0 = fmaf(w2.x, q.x, a0); a1 = fmaf(w2.y, q.y, a1);
            a2 = fmaf(w3.x, q.z, a2); a3 = fmaf(w3.y, q.w, a3);
        }
        float s = (a0 + a1) + (a2 + a3);
        s += __shfl_xor_sync(0xffffffffu, s, 1);
        if (hf == 0) sval[row] = s + xval;
        __syncthreads();

        if (tid < 32) {
            float gi = sval[tid];
            float gf = sval[32 + tid];
            float gg = sval[64 + tid];
            float go = sval[96 + tid];
            c = sigm(gf)*c + sigm(gi)*tanhf(gg);
            float h = sigm(go)*tanhf(c);
            if (t == T_-1) {
                g_hbuf[0][b][j0 + tid] = h;
            } else {
                int jg = j0 + tid;
                int hfd = jg >> 8, kd = jg & 255;
                unsigned dst = hbuf_addr + (unsigned)(((t + 1) & 1)*(2*HSEC) + hfd*HSEC + kd)*4u;
                #pragma unroll
                for (int q = 0; q < CLU; q++)
                    dsmem_store_f32(dst, (unsigned)q, h);
            }
        }
        if (t < T_-1) {
            xval = __ldcg(xp + (size_t)(t + 1)*G4_);
            asm volatile("barrier.cluster.arrive.aligned;" ::: "memory");
            asm volatile("barrier.cluster.wait.aligned;" ::: "memory");
        }
    }
    asm volatile("barrier.cluster.arrive.aligned;" ::: "memory");
    asm volatile("barrier.cluster.wait.aligned;" ::: "memory");
}

// ---------------- final fc -----------------------------------------------------
__global__ void fc_kernel(const float* __restrict__ fc_w,
                          const float* __restrict__ fc_b,
                          float* __restrict__ out)
{
    int tid = threadIdx.x;
    if (tid < B_*C_) {
        int b = tid >> 3, c = tid & 7;
        const float* h = g_hbuf[0][b];
        const float* w = fc_w + c*LH_;
        float acc = 0.f;
        for (int j = 0; j < LH_; j++) acc += h[j] * w[j];
        out[b*C_ + c] = acc + fc_b[c];
    }
}

// ---------------- launch -------------------------------------------------------
extern "C" void kernel_launch(void* const* d_in, const int* in_sizes, int n_in,
                              void* d_out, int out_size)
{
    (void)in_sizes; (void)n_in; (void)out_size;
    const float* x    = (const float*)d_in[0];
    const int*   ei   = (const int*)d_in[1];
    const float* Wl1  = (const float*)d_in[2];
    const float* Wr1  = (const float*)d_in[3];
    const float* att1 = (const float*)d_in[4];
    const float* b1   = (const float*)d_in[5];
    const float* Wl2  = (const float*)d_in[6];
    const float* Wr2  = (const float*)d_in[7];
    const float* att2 = (const float*)d_in[8];
    const float* b2   = (const float*)d_in[9];
    const float* W_ih = (const float*)d_in[10];
    const float* W_hh = (const float*)d_in[11];
    const float* b_ih = (const float*)d_in[12];
    const float* b_hh = (const float*)d_in[13];
    const float* fc_w = (const float*)d_in[14];
    const float* fc_b = (const float*)d_in[15];
    float* out = (float*)d_out;

    const size_t sm1 = (size_t)(2*N_*KHP_ + 2*F_*KH_ + 2*KH_ + N_*F_ + E_*K_) * 4
                     + (size_t)(2*E_ + (N_+1) + E_) * 4;
    const size_t sm2 = (size_t)(2*N_*HLD + 2*32*WLD) * 2
                     + (size_t)(2*N_*XP + KH_ + H_ + E_*K_) * 4
                     + (size_t)(3*E_ + (N_+1)) * 4;
    const size_t sml = SW_BYTES + (size_t)(2*(2*HSEC) + LROWS) * 4;

    cudaFuncSetAttribute(gat1_kernel, cudaFuncAttributeMaxDynamicSharedMemorySize, (int)sm1);
    cudaFuncSetAttribute(gat2_kernel, cudaFuncAttributeMaxDynamicSharedMemorySize, (int)sm2);
    cudaFuncSetAttribute(lstm_cluster_kernel, cudaFuncAttributeMaxDynamicSharedMemorySize, (int)sml);
    cudaFuncSetAttribute(lstm_cluster_kernel, cudaFuncAttributeNonPortableClusterSizeAllowed, 1);

    build_csr_kernel<<<1, 64>>>(ei);
    gat1_kernel<<<G_, 256, sm1>>>(x, ei, Wl1, Wr1, att1, b1);
    gat2_kernel<<<G_, 256, sm2>>>(ei, Wl2, Wr2, att2, b2);
    xw_bf16_kernel<<<dim3(G4_/64, G_/64), 128>>>(W_ih, b_ih, b_hh);

    {
        cudaLaunchConfig_t cfg = {};
        cfg.gridDim  = dim3(B_*CLU, 1, 1);     // 64 CTAs = 4 clusters of 16
        cfg.blockDim = dim3(256, 1, 1);
        cfg.dynamicSmemBytes = sml;
        cfg.stream = 0;
        cudaLaunchAttribute attrs[1];
        attrs[0].id = cudaLaunchAttributeClusterDimension;
        attrs[0].val.clusterDim.x = CLU;
        attrs[0].val.clusterDim.y = 1;
        attrs[0].val.clusterDim.z = 1;
        cfg.attrs = attrs;
        cfg.numAttrs = 1;
        cudaLaunchKernelEx(&cfg, lstm_cluster_kernel, W_hh);
    }

    fc_kernel<<<1, 32>>>(fc_w, fc_b, out);
}